// round 5
// baseline (speedup 1.0000x reference)
#include <cuda_runtime.h>
#include <cstdint>

typedef unsigned long long ull;

#define NCH 128
#define HW  14
#define NJ  32
#define NT  896              // tiles: 1792 (n,h) slices / 2 per tile
#define NBLK 444             // 148 SMs * 3 CTAs
#define THREADS 128

#define WS_FLOATS (128 * 104)                    // W: 128 i-rows x (32j x 3 taps + 8 pad) = 53248 B
#define XS_F2     (128 * 18)                     // x: 128 rows x (16 pos + 2 pad) float2 = 18432 B
#define SMEM_BYTES (WS_FLOATS * 4 + XS_F2 * 8)   // 71680 B -> 3 CTAs/SM

// Pre-transposed W (global), layout ws[ri*104 + 3*j + k] with ri = 4*(i%32) + i/32.
__device__ __align__(16) float W3g[WS_FLOATS];
__device__ unsigned int g_ctr;

__global__ void prep_kernel(const float* __restrict__ W) {
    int idx = blockIdx.x * blockDim.x + threadIdx.x;
    if (idx == 0) g_ctr = NBLK;                  // reset work-steal counter every launch
    if (idx < WS_FLOATS) {
        int ri = idx / 104, c = idx % 104;
        float v = 0.f;
        if (c < 96) {
            int j = c / 3, kk = c % 3;
            int i = 32 * (ri & 3) + (ri >> 2);   // inverse of ri = 4*(i%32) + i/32
            v = W[j * 384 + kk * 128 + i];       // W[j, kk, i]
        }
        W3g[idx] = v;
    }
}

__device__ __forceinline__ ull pack2(float v) {
    ull r; asm("mov.b64 %0, {%1, %1};" : "=l"(r) : "f"(v)); return r;
}
__device__ __forceinline__ void fma2(ull& d, ull a, ull b) {
    asm("fma.rn.f32x2 %0, %1, %2, %0;" : "+l"(d) : "l"(a), "l"(b));
}
__device__ __forceinline__ void add2(ull& d, ull a) {
    asm("add.rn.f32x2 %0, %0, %1;" : "+l"(d) : "l"(a));
}
__device__ __forceinline__ float lo32(ull a) { return __uint_as_float((unsigned)a); }
__device__ __forceinline__ float hi32(ull a) { return __uint_as_float((unsigned)(a >> 32)); }

// Prefetch one tile's two x rows (logical channel li) into registers.
__device__ __forceinline__ void stage_load(const float* __restrict__ x, int tile, int li,
                                           float2 (&b0)[7], float2 (&b1)[7]) {
    int s0 = tile * 2, s1 = s0 + 1;
    int n0 = s0 / 14, h0 = s0 % 14;
    int n1 = s1 / 14, h1 = s1 % 14;
    const float2* p0 = (const float2*)(x + ((n0 * NCH + li) * HW + h0) * HW);
    const float2* p1 = (const float2*)(x + ((n1 * NCH + li) * HW + h1) * HW);
#pragma unroll
    for (int m = 0; m < 7; ++m) { b0[m] = __ldcs(p0 + m); b1[m] = __ldcs(p1 + m); }
}

__global__ void __launch_bounds__(THREADS, 3)
conv3_kernel(const float* __restrict__ x, float* __restrict__ out) {
    extern __shared__ float smem[];
    float*  ws = smem;                         // [128 ri][104]
    float2* xs = (float2*)(smem + WS_FLOATS);  // [128 ri][18] : pos 0..15 (+2 pad)
    __shared__ int s_next;

    const int t = threadIdx.x;
    const int j = t >> 2;          // 0..31 output channel (8 per warp)
    const int k = t & 3;           // k-split lane: i in [32k, 32k+32)

    // ---- stage W into smem once (persistent CTA), coalesced float4 ----
    {
        const float4* src = (const float4*)W3g;
        float4* dst = (float4*)ws;
        for (int m = t; m < WS_FLOATS / 4; m += THREADS) dst[m] = src[m];
    }
    // ---- zero pad positions (never rewritten) ----
    xs[t * 18 + 0]  = make_float2(0.f, 0.f);
    xs[t * 18 + 15] = make_float2(0.f, 0.f);

    // thread t stages physical row ri=t, logical channel li = 32*(t%4) + t/4
    const int li = 32 * (t & 3) + (t >> 2);

    float2 b0[7], b1[7];
    int tile = blockIdx.x;
    stage_load(x, tile, li, b0, b1);

    while (tile < NT) {
        __syncthreads();                       // previous compute done reading xs
        // ---- STS staged tile: xs[t][p(w)] = (slice0[w], slice1[w]) ----
        {
            float2* row = xs + t * 18;
#pragma unroll
            for (int w = 0; w < 14; ++w) {
                int p = (w == 13) ? 1 : (w + 2);        // width-roll(+1) + pad offset
                float a = (w & 1) ? b0[w >> 1].y : b0[w >> 1].x;
                float b = (w & 1) ? b1[w >> 1].y : b1[w >> 1].x;
                row[p] = make_float2(a, b);
            }
        }
        if (t == 0) s_next = atomicAdd(&g_ctr, 1);
        __syncthreads();                       // xs ready, s_next visible
        int nxt = s_next;
        if (nxt < NT) stage_load(x, nxt, li, b0, b1);   // overlaps compute below

        // ---- compute: 32 K-steps over i = 32k + s ----
        ull acc[14];
#pragma unroll
        for (int w = 0; w < 14; ++w) acc[w] = 0ull;

        const float2* xr = xs + k * 18;        // physical row 4*step + k, step=0
        const float*  wr = ws + k * 104 + 3 * j;
#pragma unroll 4
        for (int s = 0; s < 32; ++s) {
            ull X[16];
#pragma unroll
            for (int q = 0; q < 8; ++q) {
                ulonglong2 v = *(const ulonglong2*)(xr + 2 * q);
                X[2 * q] = v.x; X[2 * q + 1] = v.y;
            }
            // three scalar LDS.32 (4B-aligned; (8k + 3j + c) mod 32 injective per warp)
            float wa = wr[0], wb = wr[1], wc = wr[2];
            ull W0 = pack2(wa), W1 = pack2(wb), W2 = pack2(wc);
#pragma unroll
            for (int w = 0; w < 14; ++w) {
                fma2(acc[w], W0, X[w]);
                fma2(acc[w], W1, X[w + 1]);
                fma2(acc[w], W2, X[w + 2]);
            }
            xr += 72;      // 4 rows * 18 float2
            wr += 416;     // 4 rows * 104 floats
        }

        // ---- butterfly-reduce the 4 k lanes ----
#pragma unroll
        for (int r = 1; r <= 2; r <<= 1) {
#pragma unroll
            for (int w = 0; w < 14; ++w) {
                ull o = __shfl_xor_sync(0xffffffffu, acc[w], r);
                add2(acc[w], o);
            }
        }

        // ---- write: lane k=0 -> slice0 (lo), k=1 -> slice1 (hi); height-roll(+1) ----
        if (k < 2) {
            int slice = tile * 2 + k;
            int n = slice / 14, h = slice % 14;
            int h2 = (h + 1 == 14) ? 0 : h + 1;
            float* op = out + ((n * NJ + j) * HW + h2) * HW;
#pragma unroll
            for (int w = 0; w < 14; ++w)
                op[w] = (k == 0) ? lo32(acc[w]) : hi32(acc[w]);
        }
        tile = nxt;
    }
}

extern "C" void kernel_launch(void* const* d_in, const int* in_sizes, int n_in,
                              void* d_out, int out_size) {
    const float* x = (const float*)d_in[0];   // (128,128,14,14) fp32
    const float* W = (const float*)d_in[1];   // (32,3,128) fp32
    float* out = (float*)d_out;               // (128,32,14,14) fp32

    prep_kernel<<<14, 1024>>>(W);

    cudaFuncSetAttribute(conv3_kernel,
                         cudaFuncAttributeMaxDynamicSharedMemorySize, SMEM_BYTES);
    conv3_kernel<<<NBLK, THREADS, SMEM_BYTES>>>(x, out);
}